// round 15
// baseline (speedup 1.0000x reference)
#include <cuda_runtime.h>
#include <cstdint>

#define Bn   64
#define Cc   256
#define Hh   28
#define WW   28
#define HW   784
#define NPIX 50176
#define KTOT 2304
#define NELEM 12845056

#define NT   196              // 14x14 winograd tiles per image
#define MT   12544            // Bn*NT
#define PLANE 3211264         // MT*Cc

#define WAST 272              // 256B data + 16B pad
#define WM   128              // CTA M tile (winograd tiles)
#define WSTG ((WM+64)*WAST)   // A(128 rows) + B(64 rows) = 52224
#define WSMEM (3*WSTG)        // 156672 (also >= 140KB epilogue staging)

#define RXB 1024
#define RWB 18
#define RTOT (RXB + 2*RWB)

// ---------------- scratch ----------------
__device__ int8_t g_xq[(size_t)NPIX*Cc];
__device__ int8_t g_hq[(size_t)NPIX*Cc];
__device__ int8_t g_ww1[16*Cc*Cc];        // [pos][co][ci]
__device__ int8_t g_ww2[16*Cc*Cc];
__device__ int8_t g_Xw[(size_t)16*PLANE]; // [pos][tile][ci]
__device__ float  g_h [(size_t)NPIX*Cc];  // conv1 output NHWC fp32
__device__ float  g_inv1[Cc], g_bias1[Cc], g_inv2[Cc], g_bias2[Cc];
__device__ float  g_bmax[RTOT];
__device__ unsigned g_maxbits[4];         // [3]: max|h|
__device__ float  g_scale[3];
__device__ float  g_alpha[3];
__device__ unsigned g_cnt;

__constant__ int c_CA0[4] = {1,1,1,0};    // A^T row a=0
__constant__ int c_CA1[4] = {0,1,-1,-1};  // A^T row a=1

// ---------------- helpers ----------------
__device__ __forceinline__ unsigned smem_u32(const void* p){
  unsigned a;
  asm("{ .reg .u64 t; cvta.to.shared.u64 t, %1; cvt.u32.u64 %0, t; }" : "=r"(a) : "l"(p));
  return a;
}
__device__ __forceinline__ void cp16(void* sm, const void* g){
  unsigned sa = smem_u32(sm);
  asm volatile("cp.async.cg.shared.global [%0], [%1], 16;\n" :: "r"(sa), "l"(g));
}
__device__ __forceinline__ void cp_commitg(){ asm volatile("cp.async.commit_group;\n"); }
template<int N> __device__ __forceinline__ void cp_wait(){ asm volatile("cp.async.wait_group %0;\n"::"n"(N)); }
__device__ __forceinline__ void ldm4(uint32_t &r0, uint32_t &r1, uint32_t &r2, uint32_t &r3, unsigned a){
  asm volatile("ldmatrix.sync.aligned.m8n8.x4.shared.b16 {%0,%1,%2,%3}, [%4];"
    : "=r"(r0),"=r"(r1),"=r"(r2),"=r"(r3) : "r"(a));
}

// ---------------- #1: merged reduce + prep (last-block pattern) ----------------
__global__ void reduce_prep_kernel(const float* __restrict__ x,
                                   const float* __restrict__ w1,
                                   const float* __restrict__ w2,
                                   const float* __restrict__ g1, const float* __restrict__ b1,
                                   const float* __restrict__ m1, const float* __restrict__ v1,
                                   const float* __restrict__ g2, const float* __restrict__ b2,
                                   const float* __restrict__ m2, const float* __restrict__ v2){
  int b = blockIdx.x;
  const float4* p4;
  int n4, nb, lb;
  if (b < RXB){          p4 = (const float4*)x;  n4 = NELEM/4;     nb = RXB; lb = b; }
  else if (b < RXB+RWB){ p4 = (const float4*)w1; n4 = (Cc*KTOT)/4; nb = RWB; lb = b - RXB; }
  else {                 p4 = (const float4*)w2; n4 = (Cc*KTOT)/4; nb = RWB; lb = b - RXB - RWB; }
  float m = 0.f;
  for (int i = lb*blockDim.x + threadIdx.x; i < n4; i += nb*blockDim.x){
    float4 v = p4[i];
    m = fmaxf(m, fmaxf(fmaxf(fabsf(v.x),fabsf(v.y)), fmaxf(fabsf(v.z),fabsf(v.w))));
  }
  #pragma unroll
  for (int o=16;o;o>>=1) m = fmaxf(m, __shfl_xor_sync(0xffffffffu, m, o));
  __shared__ float sm[8];
  __shared__ unsigned s_last;
  if ((threadIdx.x & 31) == 0) sm[threadIdx.x>>5] = m;
  __syncthreads();
  if (threadIdx.x == 0){
    #pragma unroll
    for (int i=1;i<8;i++) m = fmaxf(m, sm[i]);
    g_bmax[b] = m;
    __threadfence();
    s_last = (atomicAdd(&g_cnt, 1u) == RTOT-1);
  }
  __syncthreads();
  if (!s_last) return;

  int t = threadIdx.x, lane = t & 31, wid = t >> 5;
  float mx = fmaxf(fmaxf(g_bmax[t], g_bmax[t+256]), fmaxf(g_bmax[t+512], g_bmax[t+768]));
  #pragma unroll
  for (int o=16;o;o>>=1) mx = fmaxf(mx, __shfl_xor_sync(0xffffffffu, mx, o));
  if (lane == 0) sm[wid] = mx;
  __syncthreads();
  if (t == 0){
    #pragma unroll
    for (int i=1;i<8;i++) mx = fmaxf(mx, sm[i]);
    float a = mx + 1e-12f;
    g_alpha[0] = a;  g_scale[0] = a / 7.0f;
    g_maxbits[3] = 0u;
    g_cnt = 0u;
  }
  if (wid == 1){
    float a1 = (lane < RWB) ? g_bmax[RXB + lane]       : 0.f;
    float a2 = (lane < RWB) ? g_bmax[RXB + RWB + lane] : 0.f;
    #pragma unroll
    for (int o=16;o;o>>=1){
      a1 = fmaxf(a1, __shfl_xor_sync(0xffffffffu, a1, o));
      a2 = fmaxf(a2, __shfl_xor_sync(0xffffffffu, a2, o));
    }
    if (lane == 0){
      float aa1 = a1 + 1e-12f, aa2 = a2 + 1e-12f;
      g_alpha[1] = aa1;  g_scale[1] = aa1 / 7.0f;
      g_alpha[2] = aa2;  g_scale[2] = aa2 / 7.0f;
    }
  }
  {
    int c = t;
    float i1 = g1[c] / sqrtf(v1[c] + 1e-5f);
    g_inv1[c] = i1;  g_bias1[c] = b1[c] - m1[c]*i1;
    float i2 = g2[c] / sqrtf(v2[c] + 1e-5f);
    g_inv2[c] = i2;  g_bias2[c] = b2[c] - m2[c]*i2;
  }
}

// ---------------- #2: quantize+winograd weights, quantize x ----------------
__global__ void quant_all_kernel(const float* __restrict__ w1, const float* __restrict__ w2,
                                 const float* __restrict__ x){
  __shared__ float tile[32][33];
  int b = blockIdx.x, tid = threadIdx.x;
  if (b < 512){
    int which = 1 + (b >> 8);
    const float* w = (which == 1) ? w1 : w2;
    int8_t* dst = (which == 1) ? g_ww1 : g_ww2;
    int co = b & 255, ci = tid;
    float alpha = g_alpha[which];
    float s = g_scale[which];
    const float* wp = w + ((size_t)(co*Cc + ci))*9;
    int q[9];
    #pragma unroll
    for (int r=0;r<9;r++){
      float v = fminf(fmaxf(wp[r], -alpha), alpha);
      q[r] = __float2int_rn(v / s);
    }
    int U[4][3];
    #pragma unroll
    for (int j=0;j<3;j++){
      U[0][j] = 2*q[j];
      U[1][j] = q[j] + q[3+j] + q[6+j];
      U[2][j] = q[j] - q[3+j] + q[6+j];
      U[3][j] = 2*q[6+j];
    }
    #pragma unroll
    for (int i=0;i<4;i++){
      int Wr[4];
      Wr[0] = 2*U[i][0];
      Wr[1] = U[i][0] + U[i][1] + U[i][2];
      Wr[2] = U[i][0] - U[i][1] + U[i][2];
      Wr[3] = 2*U[i][2];
      #pragma unroll
      for (int j=0;j<4;j++)
        dst[(i*4+j)*(Cc*Cc) + co*Cc + ci] = (int8_t)Wr[j];
    }
  } else {
    int bb = b - 512;
    int n = bb/200; int r = bb - n*200; int by = r/25; int bx = r - by*25;
    float alpha = g_alpha[0];
    float s = g_scale[0];
    int hw0 = bx*32, c0 = by*32;
    int tx = tid & 31, ty = tid >> 5;
    #pragma unroll
    for (int j=0;j<4;j++){
      int c = c0 + ty + j*8, hw = hw0 + tx;
      tile[ty + j*8][tx] = (hw < HW) ? x[((size_t)n*Cc + c)*HW + hw] : 0.f;
    }
    __syncthreads();
    #pragma unroll
    for (int j=0;j<4;j++){
      int hw = hw0 + ty + j*8, c = c0 + tx;
      if (hw < HW){
        float v = tile[tx][ty + j*8];
        v = fminf(fmaxf(v, -alpha), alpha);
        g_xq[((size_t)n*HW + hw)*Cc + c] = (int8_t)__float2int_rn(v / s);
      }
    }
  }
}

// ---------------- activation winograd transform: SIMD-in-register (uchar4) ----------------
__global__ void xtrans_kernel(int which){
  const int8_t* __restrict__ src = which ? g_hq : g_xq;
  int t = blockIdx.x*4 + (threadIdx.x >> 6);
  int ci4 = (threadIdx.x & 63) << 2;
  int n = t/NT; int tt = t - n*NT; int ti = tt/14; int tj = tt - ti*14;
  int h0 = 2*ti - 1, w0 = 2*tj - 1;
  const int8_t* base = src + (size_t)n*HW*Cc + ci4;
  unsigned d[4][4];
  #pragma unroll
  for (int di=0; di<4; di++){
    int h = h0 + di;
    bool vh = ((unsigned)h < (unsigned)Hh);
    #pragma unroll
    for (int dj=0; dj<4; dj++){
      int w = w0 + dj;
      bool v = vh && ((unsigned)w < (unsigned)WW);
      d[di][dj] = v ? *(const unsigned*)(base + ((size_t)(h*WW + w))*Cc) : 0u;
    }
  }
  unsigned U[4][4];
  #pragma unroll
  for (int j=0;j<4;j++){
    U[0][j] = __vsub4(d[0][j], d[2][j]);
    U[1][j] = __vadd4(d[1][j], d[2][j]);
    U[2][j] = __vsub4(d[2][j], d[1][j]);
    U[3][j] = __vsub4(d[1][j], d[3][j]);
  }
  size_t rowoff = (size_t)t*Cc + ci4;
  #pragma unroll
  for (int i=0;i<4;i++){
    *(unsigned*)(g_Xw + (size_t)(i*4+0)*PLANE + rowoff) = __vsub4(U[i][0], U[i][2]);
    *(unsigned*)(g_Xw + (size_t)(i*4+1)*PLANE + rowoff) = __vadd4(U[i][1], U[i][2]);
    *(unsigned*)(g_Xw + (size_t)(i*4+2)*PLANE + rowoff) = __vsub4(U[i][2], U[i][1]);
    *(unsigned*)(g_Xw + (size_t)(i*4+3)*PLANE + rowoff) = __vsub4(U[i][1], U[i][3]);
  }
}

__global__ void quant_h_kernel(){
  int i = blockIdx.x*blockDim.x + threadIdx.x;
  if (i >= NELEM/4) return;
  float alpha = __uint_as_float(g_maxbits[3]) + 1e-12f;
  float s = alpha / 7.0f;
  float4 v = ((const float4*)g_h)[i];
  char4 q;
  q.x = (int8_t)__float2int_rn(fminf(fmaxf(v.x,-alpha),alpha) / s);
  q.y = (int8_t)__float2int_rn(fminf(fmaxf(v.y,-alpha),alpha) / s);
  q.z = (int8_t)__float2int_rn(fminf(fmaxf(v.z,-alpha),alpha) / s);
  q.w = (int8_t)__float2int_rn(fminf(fmaxf(v.w,-alpha),alpha) / s);
  ((char4*)g_hq)[i] = q;
}

#define FOLD(AB, CC) do{ int _cc=(CC); if(_cc==1){ \
  _Pragma("unroll") for(int _i=0;_i<2;_i++) _Pragma("unroll") for(int _j=0;_j<2;_j++) \
  _Pragma("unroll") for(int _e=0;_e<4;_e++) fin[_i][_j][_e][AB] += acc[_i][_j][_e]; \
 } else if(_cc==-1){ \
  _Pragma("unroll") for(int _i=0;_i<2;_i++) _Pragma("unroll") for(int _j=0;_j<2;_j++) \
  _Pragma("unroll") for(int _e=0;_e<4;_e++) fin[_i][_j][_e][AB] -= acc[_i][_j][_e]; \
 } }while(0)

// ---------------- winograd GEMM conv: 512 threads, CTA tile 128x64, grid (98, 4) ----------------
// MODE 1: epilogue BN1+hardtanh -> smem stage -> coalesced NHWC g_h + max|h|
// MODE 2: fused epilogue: +residual, BN2, hardtanh -> out NCHW (conflict-free stage)
template<int MODE>
__global__ void __launch_bounds__(512,1) winconv_kernel(const float* __restrict__ xres,
                                                        float* __restrict__ outp){
  extern __shared__ char dsm[];
  const int8_t* __restrict__ Bw = (MODE==1) ? g_ww1 : g_ww2;
  __shared__ float s_inv[64], s_bias[64];
  int tid = threadIdx.x, lane = tid & 31, wid = tid >> 5;
  int mb0 = blockIdx.x*WM, nb = blockIdx.y*64;
  if (tid < 64){
    s_inv[tid]  = (MODE==1) ? g_inv1[nb+tid]  : g_inv2[nb+tid];
    s_bias[tid] = (MODE==1) ? g_bias1[nb+tid] : g_bias2[nb+tid];
  }

  int row = tid >> 4, seg = tid & 15;     // 32 rows x 16 segs of 16B
  auto loadChunk = [&](int pos, int st){
    char* Ab = dsm + st*WSTG;
    char* Bb = Ab + WM*WAST;
    size_t aoffg = (size_t)pos*PLANE + (seg<<4);
    size_t boffg = (size_t)pos*(Cc*Cc) + (seg<<4);
    #pragma unroll
    for (int r=0;r<4;r++){
      int rr = row + r*32;
      cp16(Ab + rr*WAST + (seg<<4), g_Xw + aoffg + (size_t)(mb0+rr)*Cc);
    }
    #pragma unroll
    for (int r=0;r<2;r++){
      int rr = row + r*32;
      cp16(Bb + rr*WAST + (seg<<4), Bw + boffg + (size_t)(nb+rr)*Cc);
    }
  };

  int acc[2][2][4];
  int fin[2][2][4][4];
  #pragma unroll
  for (int i=0;i<2;i++)
    #pragma unroll
    for (int j=0;j<2;j++)
      #pragma unroll
      for (int e=0;e<4;e++){
        acc[i][j][e] = 0;
        #pragma unroll
        for (int ab=0;ab<4;ab++) fin[i][j][e][ab] = 0;
      }

  int wm = wid & 3, wn = wid >> 2;        // 4 m-groups x 4 n-groups
  int lr = (lane & 7) + ((lane >> 3) & 1)*8;
  int bo = (lane >> 4)*16;
  unsigned sbase = smem_u32(dsm);
  unsigned aoff = (unsigned)((wm*32 + lr)*WAST + bo);
  unsigned boff = (unsigned)(WM*WAST + (wn*16 + lr)*WAST + bo);

  loadChunk(0,0); cp_commitg();
  loadChunk(1,1); cp_commitg();

  #pragma unroll 1
  for (int pi=0; pi<4; pi++){
    int a0 = c_CA0[pi], a1 = c_CA1[pi];
    #pragma unroll
    for (int pj=0; pj<4; pj++){
      int pos = pi*4 + pj;
      if (pos < 15) cp_wait<1>(); else cp_wait<0>();
      __syncthreads();
      if (pos + 2 < 16){ loadChunk(pos+2, (pos+2)%3); cp_commitg(); }
      unsigned stb = sbase + (pos % 3)*WSTG;
      #pragma unroll
      for (int kk=0; kk<256; kk+=32){
        uint32_t a[2][4], b[2][2];
        #pragma unroll
        for (int im=0; im<2; im++)
          ldm4(a[im][0], a[im][1], a[im][2], a[im][3],
               stb + aoff + (unsigned)(im*16*WAST + kk));
        {
          uint32_t q0,q1,q2,q3;
          ldm4(q0,q1,q2,q3, stb + boff + (unsigned)kk);
          b[0][0]=q0; b[1][0]=q1; b[0][1]=q2; b[1][1]=q3;
        }
        #pragma unroll
        for (int im=0; im<2; im++)
          #pragma unroll
          for (int in_=0; in_<2; in_++){
            asm volatile("mma.sync.aligned.m16n8k32.row.col.s32.s8.s8.s32 "
              "{%0,%1,%2,%3},{%4,%5,%6,%7},{%8,%9},{%0,%1,%2,%3};\n"
              : "+r"(acc[im][in_][0]),"+r"(acc[im][in_][1]),
                "+r"(acc[im][in_][2]),"+r"(acc[im][in_][3])
              : "r"(a[im][0]),"r"(a[im][1]),"r"(a[im][2]),"r"(a[im][3]),
                "r"(b[in_][0]),"r"(b[in_][1]));
          }
      }
      {
        const int b0 = (pj==0) ? 1 : (pj==1) ? 1 : (pj==2) ? 1 : 0;
        const int b1 = (pj==0) ? 0 : (pj==1) ? 1 : (pj==2) ? -1 : -1;
        if (b0 != 0){ FOLD(0, a0*b0); FOLD(2, a1*b0); }
        if (b1 != 0){ FOLD(1, a0*b1); FOLD(3, a1*b1); }
        #pragma unroll
        for (int _i=0;_i<2;_i++)
          #pragma unroll
          for (int _j=0;_j<2;_j++)
            #pragma unroll
            for (int _e=0;_e<4;_e++) acc[_i][_j][_e] = 0;
      }
    }
  }
  __syncthreads();   // smem free for epilogue reuse

  float sprod4;
  if (MODE == 1){
    sprod4 = g_scale[0]*g_scale[1]*0.25f;
  } else {
    float ah = __uint_as_float(g_maxbits[3]) + 1e-12f;
    sprod4 = (ah/7.0f)*g_scale[2]*0.25f;
  }

  int gq = lane >> 2, tg = lane & 3;

  if (MODE == 1){
    // stage BN1+clip into smem [(m*4+ab)*68 + c]; m 0..127 (139264 B <= WSMEM)
    float* sm_ep = (float*)dsm;
    float lmax = 0.f;
    #pragma unroll
    for (int im=0; im<2; im++)
      #pragma unroll
      for (int half=0; half<2; half++){
        int m_local = wm*32 + im*16 + gq + half*8;
        #pragma unroll
        for (int in_=0; in_<2; in_++){
          int cl = wn*16 + in_*8 + tg*2;
          #pragma unroll
          for (int ab=0; ab<4; ab++){
            float v0 = (float)fin[im][in_][half*2+0][ab] * sprod4;
            float v1 = (float)fin[im][in_][half*2+1][ab] * sprod4;
            v0 = v0*s_inv[cl]   + s_bias[cl];
            v1 = v1*s_inv[cl+1] + s_bias[cl+1];
            v0 = fminf(fmaxf(v0, -1.f), 1.f);
            v1 = fminf(fmaxf(v1, -1.f), 1.f);
            lmax = fmaxf(lmax, fmaxf(fabsf(v0), fabsf(v1)));
            *(float2*)&sm_ep[(m_local*4 + ab)*68 + cl] = make_float2(v0, v1);
          }
        }
      }
    #pragma unroll
    for (int o=16;o;o>>=1) lmax = fmaxf(lmax, __shfl_xor_sync(0xffffffffu, lmax, o));
    if (lane == 0) atomicMax(&g_maxbits[3], __float_as_uint(lmax));
    __syncthreads();
    // coalesced NHWC write: 16 threads cover 64 contiguous channels via float4
    #pragma unroll 1
    for (int it=0; it<16; it++){
      int flat = it*512 + tid;
      int c4 = flat & 15, mab = flat >> 4;     // mab 0..511
      int m = mab >> 2, ab = mab & 3;
      int t = mb0 + m;
      int n = t/NT; int tt = t - n*NT; int ti = tt/14; int tj = tt - ti*14;
      int hw = (2*ti + (ab>>1))*WW + 2*tj + (ab&1);
      float4 v = *(const float4*)&sm_ep[(m*4 + ab)*68 + c4*4];
      *(float4*)(g_h + ((size_t)n*HW + hw)*Cc + nb + c4*4) = v;
    }
  } else {
    // stage fin*s into smem [(c*4+ab)*130 + m]: conflict-free m-strided reads (133120 B)
    float* sm_ep = (float*)dsm;
    #pragma unroll
    for (int im=0; im<2; im++)
      #pragma unroll
      for (int half=0; half<2; half++){
        int m_local = wm*32 + im*16 + gq + half*8;
        #pragma unroll
        for (int in_=0; in_<2; in_++){
          int cl = wn*16 + in_*8 + tg*2;
          #pragma unroll
          for (int ab=0; ab<4; ab++){
            float v0 = (float)fin[im][in_][half*2+0][ab] * sprod4;
            float v1 = (float)fin[im][in_][half*2+1][ab] * sprod4;
            sm_ep[((cl  )*4 + ab)*130 + m_local] = v0;
            sm_ep[((cl+1)*4 + ab)*130 + m_local] = v1;
          }
        }
      }
    __syncthreads();
    // per-thread invariants: m = tid&127, a = (tid>>7)&1, c = 2*it + (tid>>8)
    {
      int m = tid & 127, a = (tid >> 7) & 1, cbase = tid >> 8;  // cbase 0..1
      int t = mb0 + m;
      int n = t/NT; int tt = t - n*NT; int ti = tt/14; int tj = tt - ti*14;
      int hw = (2*ti + a)*WW + 2*tj;
      size_t idx0 = ((size_t)n*Cc + nb + cbase)*HW + hw;
      #pragma unroll 1
      for (int blk=0; blk<4; blk++){
        float2 r[8]; float y0v[8], y1v[8];
        #pragma unroll
        for (int k=0; k<8; k++){
          int it = blk*8 + k;
          int c = it*2 + cbase;
          r[k] = *(const float2*)(xres + idx0 + (size_t)(it*2)*HW);
          y0v[k] = sm_ep[(c*4 + a*2    )*130 + m];
          y1v[k] = sm_ep[(c*4 + a*2 + 1)*130 + m];
        }
        #pragma unroll
        for (int k=0; k<8; k++){
          int it = blk*8 + k;
          int c = it*2 + cbase;
          float inv = s_inv[c], bia = s_bias[c];
          float o0 = fminf(fmaxf((y0v[k] + r[k].x)*inv + bia, -1.f), 1.f);
          float o1 = fminf(fmaxf((y1v[k] + r[k].y)*inv + bia, -1.f), 1.f);
          *(float2*)(outp + idx0 + (size_t)(it*2)*HW) = make_float2(o0, o1);
        }
      }
    }
  }
}

// ---------------- launch ----------------
extern "C" void kernel_launch(void* const* d_in, const int* in_sizes, int n_in,
                              void* d_out, int out_size){
  const float* x    = (const float*)d_in[0];
  const float* w1   = (const float*)d_in[1];
  const float* bn1g = (const float*)d_in[2];
  const float* bn1b = (const float*)d_in[3];
  const float* bn1m = (const float*)d_in[4];
  const float* bn1v = (const float*)d_in[5];
  const float* w2   = (const float*)d_in[6];
  const float* bn2g = (const float*)d_in[7];
  const float* bn2b = (const float*)d_in[8];
  const float* bn2m = (const float*)d_in[9];
  const float* bn2v = (const float*)d_in[10];
  float* out = (float*)d_out;

  static int cfg = 0;
  if (!cfg){
    cudaFuncSetAttribute(winconv_kernel<1>, cudaFuncAttributeMaxDynamicSharedMemorySize, WSMEM);
    cudaFuncSetAttribute(winconv_kernel<2>, cudaFuncAttributeMaxDynamicSharedMemorySize, WSMEM);
    cfg = 1;
  }

  reduce_prep_kernel<<<RTOT, 256>>>(x, w1, w2,
      bn1g,bn1b,bn1m,bn1v, bn2g,bn2b,bn2m,bn2v);                    // 1
  quant_all_kernel<<<512 + 12800, 256>>>(w1, w2, x);                // 2
  xtrans_kernel<<<MT/4, 256>>>(0);                                  // 3
  winconv_kernel<1><<<dim3(MT/WM, 4), 512, WSMEM>>>(x, out);        // 4 -> ncu slot 6
  quant_h_kernel<<<(NELEM/4 + 255)/256, 256>>>();                   // 5
  xtrans_kernel<<<MT/4, 256>>>(1);                                  // 6
  winconv_kernel<2><<<dim3(MT/WM, 4), 512, WSMEM>>>(x, out);        // 7
}

// round 16
// speedup vs baseline: 1.0288x; 1.0288x over previous
#include <cuda_runtime.h>
#include <cstdint>

#define Bn   64
#define Cc   256
#define Hh   28
#define WW   28
#define HW   784
#define NPIX 50176
#define KTOT 2304
#define NELEM 12845056

#define NT   196              // 14x14 winograd tiles per image
#define MT   12544            // Bn*NT
#define PLANE 3211264         // MT*Cc

#define WAST 272              // 256B data + 16B pad
#define WSTG (128*WAST)       // A(64 rows) + B(64 rows) = 34816
#define WSMEM (3*WSTG)        // 104448 (also >= 70KB epilogue staging)

#define RXB 1024
#define RWB 18
#define RTOT (RXB + 2*RWB)

// ---------------- scratch ----------------
__device__ int8_t g_xq[(size_t)NPIX*Cc];
__device__ int8_t g_hq[(size_t)NPIX*Cc];
__device__ int8_t g_ww1[16*Cc*Cc];        // [pos][co][ci]
__device__ int8_t g_ww2[16*Cc*Cc];
__device__ int8_t g_Xw[(size_t)16*PLANE]; // [pos][tile][ci]
__device__ float  g_h [(size_t)NPIX*Cc];  // conv1 output NHWC fp32
__device__ float  g_inv1[Cc], g_bias1[Cc], g_inv2[Cc], g_bias2[Cc];
__device__ float  g_bmax[RTOT];
__device__ unsigned g_maxbits[4];         // [3]: max|h|
__device__ float  g_scale[3];
__device__ float  g_alpha[3];
__device__ unsigned g_cnt;

__constant__ int c_CA0[4] = {1,1,1,0};    // A^T row a=0
__constant__ int c_CA1[4] = {0,1,-1,-1};  // A^T row a=1

// ---------------- helpers ----------------
__device__ __forceinline__ unsigned smem_u32(const void* p){
  unsigned a;
  asm("{ .reg .u64 t; cvta.to.shared.u64 t, %1; cvt.u32.u64 %0, t; }" : "=r"(a) : "l"(p));
  return a;
}
__device__ __forceinline__ void cp16(void* sm, const void* g){
  unsigned sa = smem_u32(sm);
  asm volatile("cp.async.cg.shared.global [%0], [%1], 16;\n" :: "r"(sa), "l"(g));
}
__device__ __forceinline__ void cp_commitg(){ asm volatile("cp.async.commit_group;\n"); }
template<int N> __device__ __forceinline__ void cp_wait(){ asm volatile("cp.async.wait_group %0;\n"::"n"(N)); }
__device__ __forceinline__ void ldm4(uint32_t &r0, uint32_t &r1, uint32_t &r2, uint32_t &r3, unsigned a){
  asm volatile("ldmatrix.sync.aligned.m8n8.x4.shared.b16 {%0,%1,%2,%3}, [%4];"
    : "=r"(r0),"=r"(r1),"=r"(r2),"=r"(r3) : "r"(a));
}

// ---------------- #1: merged reduce + prep (last-block pattern) ----------------
__global__ void reduce_prep_kernel(const float* __restrict__ x,
                                   const float* __restrict__ w1,
                                   const float* __restrict__ w2,
                                   const float* __restrict__ g1, const float* __restrict__ b1,
                                   const float* __restrict__ m1, const float* __restrict__ v1,
                                   const float* __restrict__ g2, const float* __restrict__ b2,
                                   const float* __restrict__ m2, const float* __restrict__ v2){
  int b = blockIdx.x;
  const float4* p4;
  int n4, nb, lb;
  if (b < RXB){          p4 = (const float4*)x;  n4 = NELEM/4;     nb = RXB; lb = b; }
  else if (b < RXB+RWB){ p4 = (const float4*)w1; n4 = (Cc*KTOT)/4; nb = RWB; lb = b - RXB; }
  else {                 p4 = (const float4*)w2; n4 = (Cc*KTOT)/4; nb = RWB; lb = b - RXB - RWB; }
  float m = 0.f;
  for (int i = lb*blockDim.x + threadIdx.x; i < n4; i += nb*blockDim.x){
    float4 v = p4[i];
    m = fmaxf(m, fmaxf(fmaxf(fabsf(v.x),fabsf(v.y)), fmaxf(fabsf(v.z),fabsf(v.w))));
  }
  #pragma unroll
  for (int o=16;o;o>>=1) m = fmaxf(m, __shfl_xor_sync(0xffffffffu, m, o));
  __shared__ float sm[8];
  __shared__ unsigned s_last;
  if ((threadIdx.x & 31) == 0) sm[threadIdx.x>>5] = m;
  __syncthreads();
  if (threadIdx.x == 0){
    #pragma unroll
    for (int i=1;i<8;i++) m = fmaxf(m, sm[i]);
    g_bmax[b] = m;
    __threadfence();
    s_last = (atomicAdd(&g_cnt, 1u) == RTOT-1);
  }
  __syncthreads();
  if (!s_last) return;

  int t = threadIdx.x, lane = t & 31, wid = t >> 5;
  float mx = fmaxf(fmaxf(g_bmax[t], g_bmax[t+256]), fmaxf(g_bmax[t+512], g_bmax[t+768]));
  #pragma unroll
  for (int o=16;o;o>>=1) mx = fmaxf(mx, __shfl_xor_sync(0xffffffffu, mx, o));
  if (lane == 0) sm[wid] = mx;
  __syncthreads();
  if (t == 0){
    #pragma unroll
    for (int i=1;i<8;i++) mx = fmaxf(mx, sm[i]);
    float a = mx + 1e-12f;
    g_alpha[0] = a;  g_scale[0] = a / 7.0f;
    g_maxbits[3] = 0u;
    g_cnt = 0u;
  }
  if (wid == 1){
    float a1 = (lane < RWB) ? g_bmax[RXB + lane]       : 0.f;
    float a2 = (lane < RWB) ? g_bmax[RXB + RWB + lane] : 0.f;
    #pragma unroll
    for (int o=16;o;o>>=1){
      a1 = fmaxf(a1, __shfl_xor_sync(0xffffffffu, a1, o));
      a2 = fmaxf(a2, __shfl_xor_sync(0xffffffffu, a2, o));
    }
    if (lane == 0){
      float aa1 = a1 + 1e-12f, aa2 = a2 + 1e-12f;
      g_alpha[1] = aa1;  g_scale[1] = aa1 / 7.0f;
      g_alpha[2] = aa2;  g_scale[2] = aa2 / 7.0f;
    }
  }
  {
    int c = t;
    float i1 = g1[c] / sqrtf(v1[c] + 1e-5f);
    g_inv1[c] = i1;  g_bias1[c] = b1[c] - m1[c]*i1;
    float i2 = g2[c] / sqrtf(v2[c] + 1e-5f);
    g_inv2[c] = i2;  g_bias2[c] = b2[c] - m2[c]*i2;
  }
}

// ---------------- #2: quantize+winograd weights (smem-staged reads), quantize x ----------------
__global__ void quant_all_kernel(const float* __restrict__ w1, const float* __restrict__ w2,
                                 const float* __restrict__ x){
  __shared__ float tile[32][33];
  __shared__ float wrow[KTOT];           // 9216 B, one co's weights staged coalesced
  int b = blockIdx.x, tid = threadIdx.x;
  if (b < 512){
    int which = 1 + (b >> 8);
    const float* w = (which == 1) ? w1 : w2;
    int8_t* dst = (which == 1) ? g_ww1 : g_ww2;
    int co = b & 255, ci = tid;
    float alpha = g_alpha[which];
    float s = g_scale[which];
    // coalesced stage: 2304 contiguous floats for this co
    const float4* wsrc = (const float4*)(w + (size_t)co*KTOT);
    #pragma unroll
    for (int i=0;i<KTOT/4/256 + 1;i++){
      int idx = i*256 + tid;
      if (idx < KTOT/4) ((float4*)wrow)[idx] = wsrc[idx];
    }
    __syncthreads();
    const float* wp = wrow + ci*9;
    int q[9];
    #pragma unroll
    for (int r=0;r<9;r++){
      float v = fminf(fmaxf(wp[r], -alpha), alpha);
      q[r] = __float2int_rn(v / s);
    }
    int U[4][3];
    #pragma unroll
    for (int j=0;j<3;j++){
      U[0][j] = 2*q[j];
      U[1][j] = q[j] + q[3+j] + q[6+j];
      U[2][j] = q[j] - q[3+j] + q[6+j];
      U[3][j] = 2*q[6+j];
    }
    #pragma unroll
    for (int i=0;i<4;i++){
      int Wr[4];
      Wr[0] = 2*U[i][0];
      Wr[1] = U[i][0] + U[i][1] + U[i][2];
      Wr[2] = U[i][0] - U[i][1] + U[i][2];
      Wr[3] = 2*U[i][2];
      #pragma unroll
      for (int j=0;j<4;j++)
        dst[(i*4+j)*(Cc*Cc) + co*Cc + ci] = (int8_t)Wr[j];
    }
  } else {
    int bb = b - 512;
    int n = bb/200; int r = bb - n*200; int by = r/25; int bx = r - by*25;
    float alpha = g_alpha[0];
    float s = g_scale[0];
    int hw0 = bx*32, c0 = by*32;
    int tx = tid & 31, ty = tid >> 5;
    #pragma unroll
    for (int j=0;j<4;j++){
      int c = c0 + ty + j*8, hw = hw0 + tx;
      tile[ty + j*8][tx] = (hw < HW) ? x[((size_t)n*Cc + c)*HW + hw] : 0.f;
    }
    __syncthreads();
    #pragma unroll
    for (int j=0;j<4;j++){
      int hw = hw0 + ty + j*8, c = c0 + tx;
      if (hw < HW){
        float v = tile[tx][ty + j*8];
        v = fminf(fmaxf(v, -alpha), alpha);
        g_xq[((size_t)n*HW + hw)*Cc + c] = (int8_t)__float2int_rn(v / s);
      }
    }
  }
}

// ---------------- activation winograd transform: SIMD-in-register (uchar4) ----------------
__global__ void xtrans_kernel(int which){
  const int8_t* __restrict__ src = which ? g_hq : g_xq;
  int t = blockIdx.x*4 + (threadIdx.x >> 6);
  int ci4 = (threadIdx.x & 63) << 2;
  int n = t/NT; int tt = t - n*NT; int ti = tt/14; int tj = tt - ti*14;
  int h0 = 2*ti - 1, w0 = 2*tj - 1;
  const int8_t* base = src + (size_t)n*HW*Cc + ci4;
  unsigned d[4][4];
  #pragma unroll
  for (int di=0; di<4; di++){
    int h = h0 + di;
    bool vh = ((unsigned)h < (unsigned)Hh);
    #pragma unroll
    for (int dj=0; dj<4; dj++){
      int w = w0 + dj;
      bool v = vh && ((unsigned)w < (unsigned)WW);
      d[di][dj] = v ? *(const unsigned*)(base + ((size_t)(h*WW + w))*Cc) : 0u;
    }
  }
  unsigned U[4][4];
  #pragma unroll
  for (int j=0;j<4;j++){
    U[0][j] = __vsub4(d[0][j], d[2][j]);
    U[1][j] = __vadd4(d[1][j], d[2][j]);
    U[2][j] = __vsub4(d[2][j], d[1][j]);
    U[3][j] = __vsub4(d[1][j], d[3][j]);
  }
  size_t rowoff = (size_t)t*Cc + ci4;
  #pragma unroll
  for (int i=0;i<4;i++){
    *(unsigned*)(g_Xw + (size_t)(i*4+0)*PLANE + rowoff) = __vsub4(U[i][0], U[i][2]);
    *(unsigned*)(g_Xw + (size_t)(i*4+1)*PLANE + rowoff) = __vadd4(U[i][1], U[i][2]);
    *(unsigned*)(g_Xw + (size_t)(i*4+2)*PLANE + rowoff) = __vsub4(U[i][2], U[i][1]);
    *(unsigned*)(g_Xw + (size_t)(i*4+3)*PLANE + rowoff) = __vsub4(U[i][1], U[i][3]);
  }
}

__global__ void quant_h_kernel(){
  int i = blockIdx.x*blockDim.x + threadIdx.x;
  if (i >= NELEM/4) return;
  float alpha = __uint_as_float(g_maxbits[3]) + 1e-12f;
  float s = alpha / 7.0f;
  float4 v = ((const float4*)g_h)[i];
  char4 q;
  q.x = (int8_t)__float2int_rn(fminf(fmaxf(v.x,-alpha),alpha) / s);
  q.y = (int8_t)__float2int_rn(fminf(fmaxf(v.y,-alpha),alpha) / s);
  q.z = (int8_t)__float2int_rn(fminf(fmaxf(v.z,-alpha),alpha) / s);
  q.w = (int8_t)__float2int_rn(fminf(fmaxf(v.w,-alpha),alpha) / s);
  ((char4*)g_hq)[i] = q;
}

#define FOLD(AB, CC) do{ int _cc=(CC); if(_cc==1){ \
  _Pragma("unroll") for(int _i=0;_i<2;_i++) _Pragma("unroll") for(int _j=0;_j<2;_j++) \
  _Pragma("unroll") for(int _e=0;_e<4;_e++) fin[_i][_j][_e][AB] += acc[_i][_j][_e]; \
 } else if(_cc==-1){ \
  _Pragma("unroll") for(int _i=0;_i<2;_i++) _Pragma("unroll") for(int _j=0;_j<2;_j++) \
  _Pragma("unroll") for(int _e=0;_e<4;_e++) fin[_i][_j][_e][AB] -= acc[_i][_j][_e]; \
 } }while(0)

// ---------------- winograd GEMM conv: grid (196, 4) ----------------
// MODE 1: epilogue BN1+hardtanh -> smem stage -> coalesced NHWC g_h + max|h|
// MODE 2: fused epilogue: +residual, BN2, hardtanh -> out NCHW (conflict-free stage)
template<int MODE>
__global__ void __launch_bounds__(256,2) winconv_kernel(const float* __restrict__ xres,
                                                        float* __restrict__ outp){
  extern __shared__ char dsm[];
  const int8_t* __restrict__ Bw = (MODE==1) ? g_ww1 : g_ww2;
  __shared__ float s_inv[64], s_bias[64];
  int tid = threadIdx.x, lane = tid & 31, wid = tid >> 5;
  int mb0 = blockIdx.x*64, nb = blockIdx.y*64;
  if (tid < 64){
    s_inv[tid]  = (MODE==1) ? g_inv1[nb+tid]  : g_inv2[nb+tid];
    s_bias[tid] = (MODE==1) ? g_bias1[nb+tid] : g_bias2[nb+tid];
  }

  int row = tid >> 4, seg = tid & 15;
  auto loadChunk = [&](int pos, int st){
    char* Ab = dsm + st*WSTG;
    char* Bb = Ab + 64*WAST;
    size_t aoffg = (size_t)pos*PLANE + (seg<<4);
    size_t boffg = (size_t)pos*(Cc*Cc) + (seg<<4);
    #pragma unroll
    for (int r=0;r<4;r++){
      int rr = row + r*16;
      cp16(Ab + rr*WAST + (seg<<4), g_Xw + aoffg + (size_t)(mb0+rr)*Cc);
      cp16(Bb + rr*WAST + (seg<<4), Bw + boffg + (size_t)(nb+rr)*Cc);
    }
  };

  int acc[2][2][4];
  int fin[2][2][4][4];
  #pragma unroll
  for (int i=0;i<2;i++)
    #pragma unroll
    for (int j=0;j<2;j++)
      #pragma unroll
      for (int e=0;e<4;e++){
        acc[i][j][e] = 0;
        #pragma unroll
        for (int ab=0;ab<4;ab++) fin[i][j][e][ab] = 0;
      }

  int lr = (lane & 7) + ((lane >> 3) & 1)*8;
  int bo = (lane >> 4)*16;
  unsigned sbase = smem_u32(dsm);
  unsigned aoff = (unsigned)(((wid & 1)*32 + lr)*WAST + bo);
  unsigned boff = (unsigned)(64*WAST + ((wid >> 1)*16 + lr)*WAST + bo);

  loadChunk(0,0); cp_commitg();
  loadChunk(1,1); cp_commitg();

  #pragma unroll 1
  for (int pi=0; pi<4; pi++){
    int a0 = c_CA0[pi], a1 = c_CA1[pi];
    #pragma unroll
    for (int pj=0; pj<4; pj++){
      int pos = pi*4 + pj;
      if (pos < 15) cp_wait<1>(); else cp_wait<0>();
      __syncthreads();
      if (pos + 2 < 16){ loadChunk(pos+2, (pos+2)%3); cp_commitg(); }
      unsigned stb = sbase + (pos % 3)*WSTG;
      #pragma unroll
      for (int kk=0; kk<256; kk+=32){
        uint32_t a[2][4], b[2][2];
        #pragma unroll
        for (int im=0; im<2; im++)
          ldm4(a[im][0], a[im][1], a[im][2], a[im][3],
               stb + aoff + (unsigned)(im*16*WAST + kk));
        {
          uint32_t q0,q1,q2,q3;
          ldm4(q0,q1,q2,q3, stb + boff + (unsigned)kk);
          b[0][0]=q0; b[1][0]=q1; b[0][1]=q2; b[1][1]=q3;
        }
        #pragma unroll
        for (int im=0; im<2; im++)
          #pragma unroll
          for (int in_=0; in_<2; in_++){
            asm volatile("mma.sync.aligned.m16n8k32.row.col.s32.s8.s8.s32 "
              "{%0,%1,%2,%3},{%4,%5,%6,%7},{%8,%9},{%0,%1,%2,%3};\n"
              : "+r"(acc[im][in_][0]),"+r"(acc[im][in_][1]),
                "+r"(acc[im][in_][2]),"+r"(acc[im][in_][3])
              : "r"(a[im][0]),"r"(a[im][1]),"r"(a[im][2]),"r"(a[im][3]),
                "r"(b[in_][0]),"r"(b[in_][1]));
          }
      }
      {
        const int b0 = (pj==0) ? 1 : (pj==1) ? 1 : (pj==2) ? 1 : 0;
        const int b1 = (pj==0) ? 0 : (pj==1) ? 1 : (pj==2) ? -1 : -1;
        if (b0 != 0){ FOLD(0, a0*b0); FOLD(2, a1*b0); }
        if (b1 != 0){ FOLD(1, a0*b1); FOLD(3, a1*b1); }
        #pragma unroll
        for (int _i=0;_i<2;_i++)
          #pragma unroll
          for (int _j=0;_j<2;_j++)
            #pragma unroll
            for (int _e=0;_e<4;_e++) acc[_i][_j][_e] = 0;
      }
    }
  }
  __syncthreads();   // smem free for epilogue reuse

  float sprod4;
  if (MODE == 1){
    sprod4 = g_scale[0]*g_scale[1]*0.25f;
  } else {
    float ah = __uint_as_float(g_maxbits[3]) + 1e-12f;
    sprod4 = (ah/7.0f)*g_scale[2]*0.25f;
  }

  int gq = lane >> 2, tg = lane & 3;

  if (MODE == 1){
    // stage BN1+clip into smem [(m*4+ab)*68 + c]; float2 writes 2-way, float4 reads clean
    float* sm_ep = (float*)dsm;     // 64*4*68*4 = 69632 <= WSMEM
    float lmax = 0.f;
    #pragma unroll
    for (int im=0; im<2; im++)
      #pragma unroll
      for (int half=0; half<2; half++){
        int m_local = (wid & 1)*32 + im*16 + gq + half*8;
        #pragma unroll
        for (int in_=0; in_<2; in_++){
          int cl = (wid >> 1)*16 + in_*8 + tg*2;
          #pragma unroll
          for (int ab=0; ab<4; ab++){
            float v0 = (float)fin[im][in_][half*2+0][ab] * sprod4;
            float v1 = (float)fin[im][in_][half*2+1][ab] * sprod4;
            v0 = v0*s_inv[cl]   + s_bias[cl];
            v1 = v1*s_inv[cl+1] + s_bias[cl+1];
            v0 = fminf(fmaxf(v0, -1.f), 1.f);
            v1 = fminf(fmaxf(v1, -1.f), 1.f);
            lmax = fmaxf(lmax, fmaxf(fabsf(v0), fabsf(v1)));
            *(float2*)&sm_ep[(m_local*4 + ab)*68 + cl] = make_float2(v0, v1);
          }
        }
      }
    #pragma unroll
    for (int o=16;o;o>>=1) lmax = fmaxf(lmax, __shfl_xor_sync(0xffffffffu, lmax, o));
    if (lane == 0) atomicMax(&g_maxbits[3], __float_as_uint(lmax));
    __syncthreads();
    // coalesced NHWC write: half-warp covers 64 contiguous channels via float4
    #pragma unroll 1
    for (int it=0; it<16; it++){
      int flat = it*256 + tid;
      int c4 = flat & 15, mab = flat >> 4;     // mab 0..255
      int m = mab >> 2, ab = mab & 3;
      int t = mb0 + m;
      int n = t/NT; int tt = t - n*NT; int ti = tt/14; int tj = tt - ti*14;
      int hw = (2*ti + (ab>>1))*WW + 2*tj + (ab&1);
      float4 v = *(const float4*)&sm_ep[(m*4 + ab)*68 + c4*4];
      *(float4*)(g_h + ((size_t)n*HW + hw)*Cc + nb + c4*4) = v;
    }
  } else {
    // stage fin*s into smem [(c*4+ab)*66 + m]: conflict-free m-strided reads
    float* sm_ep = (float*)dsm;     // 64*4*66*4 = 67584 <= WSMEM
    #pragma unroll
    for (int im=0; im<2; im++)
      #pragma unroll
      for (int half=0; half<2; half++){
        int m_local = (wid & 1)*32 + im*16 + gq + half*8;
        #pragma unroll
        for (int in_=0; in_<2; in_++){
          int cl = (wid >> 1)*16 + in_*8 + tg*2;
          #pragma unroll
          for (int ab=0; ab<4; ab++){
            float v0 = (float)fin[im][in_][half*2+0][ab] * sprod4;
            float v1 = (float)fin[im][in_][half*2+1][ab] * sprod4;
            sm_ep[((cl  )*4 + ab)*66 + m_local] = v0;
            sm_ep[((cl+1)*4 + ab)*66 + m_local] = v1;
          }
        }
      }
    __syncthreads();
    // per-thread invariants: m = tid&63, a = (tid>>6)&1, c = 2*it + (tid>>7)
    {
      int m = tid & 63, a = (tid >> 6) & 1, cbase = tid >> 7;
      int t = mb0 + m;
      int n = t/NT; int tt = t - n*NT; int ti = tt/14; int tj = tt - ti*14;
      int hw = (2*ti + a)*WW + 2*tj;
      size_t idx0 = ((size_t)n*Cc + nb + cbase)*HW + hw;
      #pragma unroll 1
      for (int blk=0; blk<4; blk++){
        float2 r[8]; float y0v[8], y1v[8];
        #pragma unroll
        for (int k=0; k<8; k++){
          int it = blk*8 + k;
          int c = it*2 + cbase;
          r[k] = *(const float2*)(xres + idx0 + (size_t)(it*2)*HW);
          y0v[k] = sm_ep[(c*4 + a*2    )*66 + m];
          y1v[k] = sm_ep[(c*4 + a*2 + 1)*66 + m];
        }
        #pragma unroll
        for (int k=0; k<8; k++){
          int it = blk*8 + k;
          int c = it*2 + cbase;
          float inv = s_inv[c], bia = s_bias[c];
          float o0 = fminf(fmaxf((y0v[k] + r[k].x)*inv + bia, -1.f), 1.f);
          float o1 = fminf(fmaxf((y1v[k] + r[k].y)*inv + bia, -1.f), 1.f);
          *(float2*)(outp + idx0 + (size_t)(it*2)*HW) = make_float2(o0, o1);
        }
      }
    }
  }
}

// ---------------- launch ----------------
extern "C" void kernel_launch(void* const* d_in, const int* in_sizes, int n_in,
                              void* d_out, int out_size){
  const float* x    = (const float*)d_in[0];
  const float* w1   = (const float*)d_in[1];
  const float* bn1g = (const float*)d_in[2];
  const float* bn1b = (const float*)d_in[3];
  const float* bn1m = (const float*)d_in[4];
  const float* bn1v = (const float*)d_in[5];
  const float* w2   = (const float*)d_in[6];
  const float* bn2g = (const float*)d_in[7];
  const float* bn2b = (const float*)d_in[8];
  const float* bn2m = (const float*)d_in[9];
  const float* bn2v = (const float*)d_in[10];
  float* out = (float*)d_out;

  static int cfg = 0;
  if (!cfg){
    cudaFuncSetAttribute(winconv_kernel<1>, cudaFuncAttributeMaxDynamicSharedMemorySize, WSMEM);
    cudaFuncSetAttribute(winconv_kernel<2>, cudaFuncAttributeMaxDynamicSharedMemorySize, WSMEM);
    cfg = 1;
  }

  reduce_prep_kernel<<<RTOT, 256>>>(x, w1, w2,
      bn1g,bn1b,bn1m,bn1v, bn2g,bn2b,bn2m,bn2v);                    // 1
  quant_all_kernel<<<512 + 12800, 256>>>(w1, w2, x);                // 2
  xtrans_kernel<<<MT/4, 256>>>(0);                                  // 3
  winconv_kernel<1><<<dim3(196, 4), 256, WSMEM>>>(x, out);          // 4 -> ncu slot 6
  quant_h_kernel<<<(NELEM/4 + 255)/256, 256>>>();                   // 5
  xtrans_kernel<<<MT/4, 256>>>(1);                                  // 6
  winconv_kernel<2><<<dim3(196, 4), 256, WSMEM>>>(x, out);          // 7
}